// round 15
// baseline (speedup 1.0000x reference)
#include <cuda_runtime.h>
#include <cuda_bf16.h>
#include <cuda_pipeline.h>
#include <mma.h>
#include <math.h>
#include <stdint.h>

using namespace nvcuda;

#define Bb 8
#define Ss 1024
#define Dd 1024
#define Hh 16
#define DHh 64
#define FFf 4096
#define LAYER 3
#define MROWS (Bb*Ss)   /* 8192 */

// ---------------- scratch (device globals; allocation-free rule) ----------------
__device__ float g_h  [MROWS*Dd];
__device__ float g_mid[MROWS*Dd];
__device__ __nv_bfloat16 g_f [(size_t)2*MROWS*FFf];  // ffn split hi|lo
__device__ __nv_bfloat16 g_Ah[(size_t)MROWS*FFf];
__device__ __nv_bfloat16 g_Al[(size_t)MROWS*FFf];
__device__ __nv_bfloat16 g_Bh[(size_t)FFf*Dd];
__device__ __nv_bfloat16 g_Bl[(size_t)FFf*Dd];
__device__ __nv_bfloat16 g_qh[MROWS*Dd];
__device__ __nv_bfloat16 g_ql[MROWS*Dd];
__device__ __nv_bfloat16 g_kh[MROWS*Dd];
__device__ __nv_bfloat16 g_kl[MROWS*Dd];
__device__ __nv_bfloat16 g_vh[MROWS*Dd];
__device__ __nv_bfloat16 g_vl[MROWS*Dd];
__device__ int   g_is64;

// ==================== dtype detection ====================
__global__ void detect_kernel(const int* __restrict__ x) {
    __shared__ int any;
    if (threadIdx.x == 0) any = 0;
    __syncthreads();
    int local = 0;
    for (int i = threadIdx.x; i < 4096; i += blockDim.x)
        if (x[2*i + 1] != 0) local = 1;
    if (local) any = 1;
    __syncthreads();
    if (threadIdx.x == 0) g_is64 = (any == 0) ? 1 : 0;
}

// ==================== embed ====================
__global__ void embed_kernel(const int* __restrict__ x, const float* __restrict__ emb,
                             const float* __restrict__ pos, float* __restrict__ h) {
    int i = blockIdx.x * blockDim.x + threadIdx.x;
    if (i >= MROWS * (Dd/4)) return;
    int row = i >> 8;
    int dc  = i & 255;
    int s   = row & (Ss - 1);
    long long tok = g_is64 ? ((const long long*)x)[row] : (long long)x[row];
    float4 e = ((const float4*)emb)[(size_t)tok * 256 + dc];
    float4 p = ((const float4*)pos)[(size_t)s   * 256 + dc];
    float4 r;
    r.x = fmaf(e.x, 32.0f, p.x);
    r.y = fmaf(e.y, 32.0f, p.y);
    r.z = fmaf(e.z, 32.0f, p.z);
    r.w = fmaf(e.w, 32.0f, p.w);
    ((float4*)h)[i] = r;
}

// ==================== layernorm with fused split-bf16 output ====================
__global__ __launch_bounds__(256)
void ln_split_kernel(const float* __restrict__ in, const float* __restrict__ gamma,
                     const float* __restrict__ beta, __nv_bfloat16* __restrict__ oh,
                     __nv_bfloat16* __restrict__ ol) {
    int row = blockIdx.x;
    int tid = threadIdx.x;
    const float4* xr = (const float4*)(in + (size_t)row * Dd);
    float4 v = xr[tid];
    float s1 = v.x + v.y + v.z + v.w;
    float s2 = v.x*v.x + v.y*v.y + v.z*v.z + v.w*v.w;
    #pragma unroll
    for (int o = 16; o; o >>= 1) {
        s1 += __shfl_xor_sync(0xffffffffu, s1, o);
        s2 += __shfl_xor_sync(0xffffffffu, s2, o);
    }
    __shared__ float a1[8], a2[8];
    int lane = tid & 31, wid = tid >> 5;
    if (lane == 0) { a1[wid] = s1; a2[wid] = s2; }
    __syncthreads();
    __shared__ float mS, invS;
    if (tid == 0) {
        float t1 = 0.f, t2 = 0.f;
        #pragma unroll
        for (int w = 0; w < 8; ++w) { t1 += a1[w]; t2 += a2[w]; }
        float mean = t1 * (1.0f / Dd);
        float var  = t2 * (1.0f / Dd) - mean * mean;
        mS = mean; invS = rsqrtf(var + 1e-5f);
    }
    __syncthreads();
    float mean = mS, inv = invS;
    float4 g4 = ((const float4*)gamma)[tid];
    float4 b4 = ((const float4*)beta)[tid];
    float o0 = (v.x - mean) * inv * g4.x + b4.x;
    float o1 = (v.y - mean) * inv * g4.y + b4.y;
    float o2 = (v.z - mean) * inv * g4.z + b4.z;
    float o3 = (v.w - mean) * inv * g4.w + b4.w;
    __nv_bfloat16 h0 = __float2bfloat16(o0), h1 = __float2bfloat16(o1);
    __nv_bfloat16 h2 = __float2bfloat16(o2), h3 = __float2bfloat16(o3);
    __nv_bfloat16 l0 = __float2bfloat16(o0 - __bfloat162float(h0));
    __nv_bfloat16 l1 = __float2bfloat16(o1 - __bfloat162float(h1));
    __nv_bfloat16 l2 = __float2bfloat16(o2 - __bfloat162float(h2));
    __nv_bfloat16 l3 = __float2bfloat16(o3 - __bfloat162float(h3));
    size_t base = (size_t)row * Dd + tid * 4;
    *(__nv_bfloat162*)(oh + base)     = __nv_bfloat162(h0, h1);
    *(__nv_bfloat162*)(oh + base + 2) = __nv_bfloat162(h2, h3);
    *(__nv_bfloat162*)(ol + base)     = __nv_bfloat162(l0, l1);
    *(__nv_bfloat162*)(ol + base + 2) = __nv_bfloat162(l2, l3);
}

// ==================== weight fp32 [K,N] -> split bf16 transposed [N,K] ====================
__global__ void convtrans_kernel(const float* __restrict__ W, __nv_bfloat16* __restrict__ TH,
                                 __nv_bfloat16* __restrict__ TL, int K, int N) {
    __shared__ float t[32][33];
    int nb = blockIdx.x * 32, kb = blockIdx.y * 32;
    int tx = threadIdx.x, ty = threadIdx.y;
    for (int r = ty; r < 32; r += 8)
        t[r][tx] = W[(size_t)(kb + r) * N + nb + tx];
    __syncthreads();
    for (int r = ty; r < 32; r += 8) {
        float v = t[tx][r];
        __nv_bfloat16 h = __float2bfloat16(v);
        __nv_bfloat16 l = __float2bfloat16(v - __bfloat162float(h));
        size_t o = (size_t)(nb + r) * K + kb + tx;
        TH[o] = h; TL[o] = l;
    }
}

// ==================== wmma split-bf16 GEMM (128x256 tile, BK=64, 512 threads) ====================
#define WTSE 72
#define WTSB 144
#define A_TILE_B (128*WTSB)
#define B_TILE_B (256*WTSB)
#define STAGE_B  (2*A_TILE_B + 2*B_TILE_B)  /* 110592 */
#define SMEM_B   (2*STAGE_B)                /* 221184 */

// EPI: 0:+bias->C  1:+bias+res->C  2:relu(+bias)->C  3:+bias->split  4:relu(+bias)->split
template<int EPI>
__global__ __launch_bounds__(512)
void bgemm_kernel(const __nv_bfloat16* __restrict__ Ah, const __nv_bfloat16* __restrict__ Al,
                  const __nv_bfloat16* __restrict__ Bh, const __nv_bfloat16* __restrict__ Bl,
                  const float* __restrict__ bias, const float* __restrict__ res,
                  float* __restrict__ C, __nv_bfloat16* __restrict__ Oh,
                  __nv_bfloat16* __restrict__ Ol, int N, int K) {
    extern __shared__ __align__(128) char smem[];
    int tid = threadIdx.x, wid = tid >> 5;
    int rowBase = blockIdx.y * 128, colBase = blockIdx.x * 256;
    // 16 warps: 2 rows x 8 cols of 64x32 warp tiles
    int m0 = (wid >> 3) * 64, n0 = (wid & 7) * 32;

    // 12 x 16B chunks per stage per thread (6144 total)
    const __nv_bfloat16* gsrc[12];
    int soff[12];
    #pragma unroll
    for (int i = 0; i < 12; ++i) {
        int v = tid + (i << 9);
        if (v < 2048) {
            int t2 = v >> 10, idx = v & 1023, row = idx >> 3, c = idx & 7;
            gsrc[i] = (t2 ? Al : Ah) + (size_t)(rowBase + row) * K + c * 8;
            soff[i] = t2 * A_TILE_B + row * WTSB + c * 16;
        } else {
            int w = v - 2048;
            int t2 = w >> 11, idx = w & 2047, row = idx >> 3, c = idx & 7;
            gsrc[i] = (t2 ? Bl : Bh) + (size_t)(colBase + row) * K + c * 8;
            soff[i] = 2 * A_TILE_B + t2 * B_TILE_B + row * WTSB + c * 16;
        }
    }

    wmma::fragment<wmma::accumulator, 16, 16, 16, float> acc[4][2];
    #pragma unroll
    for (int mf = 0; mf < 4; ++mf)
        #pragma unroll
        for (int nf = 0; nf < 2; ++nf)
            wmma::fill_fragment(acc[mf][nf], 0.0f);

    const int nch = K >> 6;
    #pragma unroll
    for (int i = 0; i < 12; ++i)
        __pipeline_memcpy_async(smem + soff[i], gsrc[i], 16);
    __pipeline_commit();
    #pragma unroll
    for (int i = 0; i < 12; ++i)
        __pipeline_memcpy_async(smem + STAGE_B + soff[i], gsrc[i] + 64, 16);
    __pipeline_commit();

    for (int ch = 0; ch < nch; ++ch) {
        if (ch + 2 <= nch) __pipeline_wait_prior(1);
        else               __pipeline_wait_prior(0);
        __syncthreads();
        char* stage = smem + (ch & 1) * STAGE_B;
        const __nv_bfloat16* At_h = (const __nv_bfloat16*)(stage);
        const __nv_bfloat16* At_l = (const __nv_bfloat16*)(stage + A_TILE_B);
        const __nv_bfloat16* Bt_h = (const __nv_bfloat16*)(stage + 2 * A_TILE_B);
        const __nv_bfloat16* Bt_l = (const __nv_bfloat16*)(stage + 2 * A_TILE_B + B_TILE_B);
        #pragma unroll
        for (int ks = 0; ks < 4; ++ks) {
            wmma::fragment<wmma::matrix_b, 16, 16, 16, __nv_bfloat16, wmma::col_major> bh[2], bl[2];
            #pragma unroll
            for (int nf = 0; nf < 2; ++nf) {
                wmma::load_matrix_sync(bh[nf], Bt_h + (n0 + nf * 16) * WTSE + ks * 16, WTSE);
                wmma::load_matrix_sync(bl[nf], Bt_l + (n0 + nf * 16) * WTSE + ks * 16, WTSE);
            }
            #pragma unroll
            for (int mf = 0; mf < 4; ++mf) {
                wmma::fragment<wmma::matrix_a, 16, 16, 16, __nv_bfloat16, wmma::row_major> fa, fl2;
                wmma::load_matrix_sync(fa,  At_h + (m0 + mf * 16) * WTSE + ks * 16, WTSE);
                wmma::load_matrix_sync(fl2, At_l + (m0 + mf * 16) * WTSE + ks * 16, WTSE);
                #pragma unroll
                for (int nf = 0; nf < 2; ++nf)
                    wmma::mma_sync(acc[mf][nf], fa, bh[nf], acc[mf][nf]);
                #pragma unroll
                for (int nf = 0; nf < 2; ++nf)
                    wmma::mma_sync(acc[mf][nf], fa, bl[nf], acc[mf][nf]);
                #pragma unroll
                for (int nf = 0; nf < 2; ++nf)
                    wmma::mma_sync(acc[mf][nf], fl2, bh[nf], acc[mf][nf]);
            }
        }
        __syncthreads();
        if (ch + 2 < nch) {
            #pragma unroll
            for (int i = 0; i < 12; ++i)
                __pipeline_memcpy_async(smem + (ch & 1) * STAGE_B + soff[i],
                                        gsrc[i] + (size_t)(ch + 2) * 64, 16);
            __pipeline_commit();
        }
    }

    float* sf = (float*)smem;
    #pragma unroll
    for (int mf = 0; mf < 4; ++mf)
        #pragma unroll
        for (int nf = 0; nf < 2; ++nf)
            wmma::store_matrix_sync(sf + (m0 + mf * 16) * 260 + n0 + nf * 16,
                                    acc[mf][nf], 260, wmma::mem_row_major);
    __syncthreads();
    #pragma unroll
    for (int i = 0; i < 16; ++i) {
        int v = tid + (i << 9);
        int r = v >> 6, c4 = (v & 63) * 4;
        float4 val = *(float4*)(sf + r * 260 + c4);
        int col = colBase + c4;
        float4 bv = *(const float4*)(bias + col);
        val.x += bv.x; val.y += bv.y; val.z += bv.z; val.w += bv.w;
        size_t o = (size_t)(rowBase + r) * N + col;
        if (EPI == 1) {
            float4 rv = *(const float4*)(res + o);
            val.x += rv.x; val.y += rv.y; val.z += rv.z; val.w += rv.w;
        }
        if (EPI == 2 || EPI == 4) {
            val.x = fmaxf(val.x, 0.f); val.y = fmaxf(val.y, 0.f);
            val.z = fmaxf(val.z, 0.f); val.w = fmaxf(val.w, 0.f);
        }
        if (EPI <= 2) {
            *(float4*)(C + o) = val;
        } else {
            __nv_bfloat16 h0 = __float2bfloat16(val.x), h1 = __float2bfloat16(val.y);
            __nv_bfloat16 h2 = __float2bfloat16(val.z), h3 = __float2bfloat16(val.w);
            __nv_bfloat16 l0 = __float2bfloat16(val.x - __bfloat162float(h0));
            __nv_bfloat16 l1 = __float2bfloat16(val.y - __bfloat162float(h1));
            __nv_bfloat16 l2 = __float2bfloat16(val.z - __bfloat162float(h2));
            __nv_bfloat16 l3 = __float2bfloat16(val.w - __bfloat162float(h3));
            *(__nv_bfloat162*)(Oh + o)     = __nv_bfloat162(h0, h1);
            *(__nv_bfloat162*)(Oh + o + 2) = __nv_bfloat162(h2, h3);
            *(__nv_bfloat162*)(Ol + o)     = __nv_bfloat162(l0, l1);
            *(__nv_bfloat162*)(Ol + o + 2) = __nv_bfloat162(l2, l3);
        }
    }
}

// ==================== fused attention (scores + softmax + ctx) ====================
#define FTSE 72
#define FTSB 144
#define FA_QH 0
#define FA_QL 18432
#define FA_KH 36864
#define FA_KL 55296
#define FA_SV 73728
#define FA_PH 141312
#define FA_PL 176128
#define FA_RS 210944
#define FA_SMEM 211456

__global__ __launch_bounds__(256)
void fattn_kernel(const __nv_bfloat16* __restrict__ qh, const __nv_bfloat16* __restrict__ ql,
                  const __nv_bfloat16* __restrict__ kh, const __nv_bfloat16* __restrict__ kl,
                  const __nv_bfloat16* __restrict__ vh, const __nv_bfloat16* __restrict__ vl_,
                  const int* __restrict__ vlen,
                  __nv_bfloat16* __restrict__ Oh, __nv_bfloat16* __restrict__ Ol) {
    extern __shared__ __align__(128) char smem[];
    int bh = blockIdx.y;
    int b = bh >> 4, hh = bh & 15;
    int i0 = blockIdx.x * 128;
    int vl = g_is64 ? (int)((const long long*)vlen)[b] : vlen[b];
    int nch = (vl + 127) >> 7;
    int tid = threadIdx.x, wid = tid >> 5, lane = tid & 31;
    int sm0 = (wid >> 2) * 64, sn0 = (wid & 3) * 32;
    int om0 = (wid >> 1) * 32, on0 = (wid & 1) * 32;
    int myrow0 = wid * 16;

    #pragma unroll
    for (int i = 0; i < 8; ++i) {
        int v = tid + (i << 8);
        int split = v >> 10, rem = v & 1023, r = rem >> 3, c = rem & 7;
        const __nv_bfloat16* src = (split ? ql : qh) + (size_t)(b * Ss + i0 + r) * Dd + hh * 64 + c * 8;
        *(uint4*)(smem + split * 18432 + r * FTSB + c * 16) = *(const uint4*)src;
    }

    wmma::fragment<wmma::accumulator, 16, 16, 16, float> oacc[2][2];
    #pragma unroll
    for (int mf = 0; mf < 2; ++mf)
        #pragma unroll
        for (int nf = 0; nf < 2; ++nf)
            wmma::fill_fragment(oacc[mf][nf], 0.0f);
    float psum[16];
    #pragma unroll
    for (int rr = 0; rr < 16; ++rr) psum[rr] = 0.f;

    for (int ch = 0; ch < nch; ++ch) {
        int j0 = ch * 128;
        #pragma unroll
        for (int i = 0; i < 8; ++i) {
            int v = tid + (i << 8);
            int split = v >> 10, rem = v & 1023, r = rem >> 3, c = rem & 7;
            const __nv_bfloat16* src = (split ? kl : kh) + (size_t)(b * Ss + j0 + r) * Dd + hh * 64 + c * 8;
            *(uint4*)(smem + FA_KH + split * 18432 + r * FTSB + c * 16) = *(const uint4*)src;
        }
        __syncthreads();
        {
            wmma::fragment<wmma::accumulator, 16, 16, 16, float> sacc[4][2];
            #pragma unroll
            for (int mf = 0; mf < 4; ++mf)
                #pragma unroll
                for (int nf = 0; nf < 2; ++nf)
                    wmma::fill_fragment(sacc[mf][nf], 0.0f);
            const __nv_bfloat16* Qh = (const __nv_bfloat16*)(smem + FA_QH);
            const __nv_bfloat16* Ql = (const __nv_bfloat16*)(smem + FA_QL);
            const __nv_bfloat16* Kh = (const __nv_bfloat16*)(smem + FA_KH);
            const __nv_bfloat16* Kl = (const __nv_bfloat16*)(smem + FA_KL);
            #pragma unroll
            for (int ks = 0; ks < 4; ++ks) {
                wmma::fragment<wmma::matrix_a, 16, 16, 16, __nv_bfloat16, wmma::row_major> ahf[4], alf[4];
                wmma::fragment<wmma::matrix_b, 16, 16, 16, __nv_bfloat16, wmma::col_major> bhf[2], blf[2];
                #pragma unroll
                for (int mf = 0; mf < 4; ++mf) {
                    wmma::load_matrix_sync(ahf[mf], Qh + (sm0 + mf * 16) * FTSE + ks * 16, FTSE);
                    wmma::load_matrix_sync(alf[mf], Ql + (sm0 + mf * 16) * FTSE + ks * 16, FTSE);
                }
                #pragma unroll
                for (int nf = 0; nf < 2; ++nf) {
                    wmma::load_matrix_sync(bhf[nf], Kh + (sn0 + nf * 16) * FTSE + ks * 16, FTSE);
                    wmma::load_matrix_sync(blf[nf], Kl + (sn0 + nf * 16) * FTSE + ks * 16, FTSE);
                }
                #pragma unroll
                for (int mf = 0; mf < 4; ++mf)
                    #pragma unroll
                    for (int nf = 0; nf < 2; ++nf) {
                        wmma::mma_sync(sacc[mf][nf], ahf[mf], bhf[nf], sacc[mf][nf]);
                        wmma::mma_sync(sacc[mf][nf], ahf[mf], blf[nf], sacc[mf][nf]);
                        wmma::mma_sync(sacc[mf][nf], alf[mf], bhf[nf], sacc[mf][nf]);
                    }
            }
            float* S = (float*)(smem + FA_SV);
            #pragma unroll
            for (int mf = 0; mf < 4; ++mf)
                #pragma unroll
                for (int nf = 0; nf < 2; ++nf) {
                    #pragma unroll
                    for (int t = 0; t < sacc[mf][nf].num_elements; ++t)
                        sacc[mf][nf].x[t] *= 0.125f;
                    wmma::store_matrix_sync(S + (sm0 + mf * 16) * 132 + sn0 + nf * 16,
                                            sacc[mf][nf], 132, wmma::mem_row_major);
                }
        }
        __syncthreads();
        {
            const float* S = (const float*)(smem + FA_SV);
            int jb = j0 + lane * 4;
            #pragma unroll
            for (int rr = 0; rr < 16; ++rr) {
                int row = myrow0 + rr;
                float4 sv = *(const float4*)(S + row * 132 + lane * 4);
                float p0 = (jb + 0 < vl) ? __expf(sv.x) : 0.f;
                float p1 = (jb + 1 < vl) ? __expf(sv.y) : 0.f;
                float p2 = (jb + 2 < vl) ? __expf(sv.z) : 0.f;
                float p3 = (jb + 3 < vl) ? __expf(sv.w) : 0.f;
                psum[rr] += (p0 + p1) + (p2 + p3);
                __nv_bfloat16 h0 = __float2bfloat16(p0), h1 = __float2bfloat16(p1);
                __nv_bfloat16 h2 = __float2bfloat16(p2), h3 = __float2bfloat16(p3);
                __nv_bfloat16 l0 = __float2bfloat16(p0 - __bfloat162float(h0));
                __nv_bfloat16 l1 = __float2bfloat16(p1 - __bfloat162float(h1));
                __nv_bfloat16 l2 = __float2bfloat16(p2 - __bfloat162float(h2));
                __nv_bfloat16 l3 = __float2bfloat16(p3 - __bfloat162float(h3));
                int po = row * 272 + lane * 8;
                *(__nv_bfloat162*)(smem + FA_PH + po)     = __nv_bfloat162(h0, h1);
                *(__nv_bfloat162*)(smem + FA_PH + po + 4) = __nv_bfloat162(h2, h3);
                *(__nv_bfloat162*)(smem + FA_PL + po)     = __nv_bfloat162(l0, l1);
                *(__nv_bfloat162*)(smem + FA_PL + po + 4) = __nv_bfloat162(l2, l3);
            }
        }
        __syncthreads();
        #pragma unroll
        for (int i = 0; i < 8; ++i) {
            int v = tid + (i << 8);
            int split = v >> 10, rem = v & 1023, r = rem >> 3, c = rem & 7;
            const __nv_bfloat16* src = (split ? vl_ : vh) + (size_t)(b * Ss + j0 + r) * Dd + hh * 64 + c * 8;
            *(uint4*)(smem + FA_SV + split * 18432 + r * FTSB + c * 16) = *(const uint4*)src;
        }
        __syncthreads();
        {
            const __nv_bfloat16* Ph = (const __nv_bfloat16*)(smem + FA_PH);
            const __nv_bfloat16* Pl = (const __nv_bfloat16*)(smem + FA_PL);
            const __nv_bfloat16* Vh = (const __nv_bfloat16*)(smem + FA_SV);
            const __nv_bfloat16* Vl = (const __nv_bfloat16*)(smem + FA_SV + 18432);
            #pragma unroll
            for (int ks = 0; ks < 8; ++ks) {
                wmma::fragment<wmma::matrix_a, 16, 16, 16, __nv_bfloat16, wmma::row_major> fph[2], fpl[2];
                wmma::fragment<wmma::matrix_b, 16, 16, 16, __nv_bfloat16, wmma::row_major> fvh[2], fvl[2];
                #pragma unroll
                for (int mf = 0; mf < 2; ++mf) {
                    wmma::load_matrix_sync(fph[mf], Ph + (om0 + mf * 16) * 136 + ks * 16, 136);
                    wmma::load_matrix_sync(fpl[mf], Pl + (om0 + mf * 16) * 136 + ks * 16, 136);
                }
                #pragma unroll
                for (int nf = 0; nf < 2; ++nf) {
                    wmma::load_matrix_sync(fvh[nf], Vh + (ks * 16) * FTSE + on0 + nf * 16, FTSE);
                    wmma::load_matrix_sync(fvl[nf], Vl + (ks * 16) * FTSE + on0 + nf * 16, FTSE);
                }
                #pragma unroll
                for (int mf = 0; mf < 2; ++mf)
                    #pragma unroll
                    for (int nf = 0; nf < 2; ++nf) {
                        wmma::mma_sync(oacc[mf][nf], fph[mf], fvh[nf], oacc[mf][nf]);
                        wmma::mma_sync(oacc[mf][nf], fph[mf], fvl[nf], oacc[mf][nf]);
                        wmma::mma_sync(oacc[mf][nf], fpl[mf], fvh[nf], oacc[mf][nf]);
                    }
            }
        }
        __syncthreads();
    }

    {
        float* rinv = (float*)(smem + FA_RS);
        #pragma unroll
        for (int rr = 0; rr < 16; ++rr) {
            float s = psum[rr];
            #pragma unroll
            for (int o = 16; o; o >>= 1) s += __shfl_xor_sync(0xffffffffu, s, o);
            if (lane == 0) rinv[myrow0 + rr] = 1.0f / s;
        }
    }
    float* sf = (float*)(smem + FA_SV);
    #pragma unroll
    for (int mf = 0; mf < 2; ++mf)
        #pragma unroll
        for (int nf = 0; nf < 2; ++nf)
            wmma::store_matrix_sync(sf + (om0 + mf * 16) * 68 + on0 + nf * 16,
                                    oacc[mf][nf], 68, wmma::mem_row_major);
    __syncthreads();
    const float* rinv = (const float*)(smem + FA_RS);
    #pragma unroll
    for (int i = 0; i < 8; ++i) {
        int v = tid + (i << 8);
        int r = v >> 4, c4 = (v & 15) * 4;
        float inv = rinv[r];
        float4 val = *(float4*)(sf + r * 68 + c4);
        val.x *= inv; val.y *= inv; val.z *= inv; val.w *= inv;
        size_t o = (size_t)(b * Ss + i0 + r) * Dd + hh * 64 + c4;
        __nv_bfloat16 h0 = __float2bfloat16(val.x), h1 = __float2bfloat16(val.y);
        __nv_bfloat16 h2 = __float2bfloat16(val.z), h3 = __float2bfloat16(val.w);
        __nv_bfloat16 l0 = __float2bfloat16(val.x - __bfloat162float(h0));
        __nv_bfloat16 l1 = __float2bfloat16(val.y - __bfloat162float(h1));
        __nv_bfloat16 l2 = __float2bfloat16(val.z - __bfloat162float(h2));
        __nv_bfloat16 l3 = __float2bfloat16(val.w - __bfloat162float(h3));
        *(__nv_bfloat162*)(Oh + o)     = __nv_bfloat162(h0, h1);
        *(__nv_bfloat162*)(Oh + o + 2) = __nv_bfloat162(h2, h3);
        *(__nv_bfloat162*)(Ol + o)     = __nv_bfloat162(l0, l1);
        *(__nv_bfloat162*)(Ol + o + 2) = __nv_bfloat162(l2, l3);
    }
}

// ==================== launch ====================
extern "C" void kernel_launch(void* const* d_in, const int* in_sizes, int n_in,
                              void* d_out, int out_size) {
    const int*   x    = (const int*)d_in[0];
    const int*   vlen = (const int*)d_in[1];
    const float* emb  = (const float*)d_in[2];
    const float* pos  = (const float*)d_in[3];
    const float* Wq = (const float*)d_in[4]  + (size_t)LAYER * Dd * Dd;
    const float* bq = (const float*)d_in[5]  + LAYER * Dd;
    const float* Wk = (const float*)d_in[6]  + (size_t)LAYER * Dd * Dd;
    const float* bk = (const float*)d_in[7]  + LAYER * Dd;
    const float* Wv = (const float*)d_in[8]  + (size_t)LAYER * Dd * Dd;
    const float* bv = (const float*)d_in[9]  + LAYER * Dd;
    const float* Wo = (const float*)d_in[10] + (size_t)LAYER * Dd * Dd;
    const float* bo = (const float*)d_in[11] + LAYER * Dd;
    const float* W1 = (const float*)d_in[12] + (size_t)LAYER * Dd * FFf;
    const float* b1 = (const float*)d_in[13] + LAYER * FFf;
    const float* W2 = (const float*)d_in[14] + (size_t)LAYER * FFf * Dd;
    const float* b2 = (const float*)d_in[15] + LAYER * Dd;
    const float* g1    = (const float*)d_in[16] + LAYER * Dd;
    const float* beta1 = (const float*)d_in[17] + LAYER * Dd;
    const float* g2    = (const float*)d_in[18] + LAYER * Dd;
    const float* beta2 = (const float*)d_in[19] + LAYER * Dd;
    float* out = (float*)d_out;

    float *h, *mid;
    __nv_bfloat16 *f, *Ah, *Al, *Bh, *Bl, *qh, *ql, *kh, *kl, *vh, *vl;
    cudaGetSymbolAddress((void**)&h,   g_h);
    cudaGetSymbolAddress((void**)&mid, g_mid);
    cudaGetSymbolAddress((void**)&f,   g_f);
    cudaGetSymbolAddress((void**)&Ah,  g_Ah);
    cudaGetSymbolAddress((void**)&Al,  g_Al);
    cudaGetSymbolAddress((void**)&Bh,  g_Bh);
    cudaGetSymbolAddress((void**)&Bl,  g_Bl);
    cudaGetSymbolAddress((void**)&qh,  g_qh);
    cudaGetSymbolAddress((void**)&ql,  g_ql);
    cudaGetSymbolAddress((void**)&kh,  g_kh);
    cudaGetSymbolAddress((void**)&kl,  g_kl);
    cudaGetSymbolAddress((void**)&vh,  g_vh);
    cudaGetSymbolAddress((void**)&vl,  g_vl);
    __nv_bfloat16* fh = f;
    __nv_bfloat16* fl = f + (size_t)MROWS * FFf;

    cudaFuncSetAttribute(bgemm_kernel<1>, cudaFuncAttributeMaxDynamicSharedMemorySize, SMEM_B);
    cudaFuncSetAttribute(bgemm_kernel<3>, cudaFuncAttributeMaxDynamicSharedMemorySize, SMEM_B);
    cudaFuncSetAttribute(bgemm_kernel<4>, cudaFuncAttributeMaxDynamicSharedMemorySize, SMEM_B);
    cudaFuncSetAttribute(fattn_kernel, cudaFuncAttributeMaxDynamicSharedMemorySize, FA_SMEM);

    detect_kernel<<<1, 256>>>(x);
    embed_kernel<<<(MROWS * (Dd/4)) / 256, 256>>>(x, emb, pos, h);
    ln_split_kernel<<<MROWS, 256>>>(h, g1, beta1, Ah, Al);

    dim3 blkT(32, 8);
    dim3 gdd(Dd / 256, MROWS / 128);           // (4, 64)

    convtrans_kernel<<<dim3(Dd/32, Dd/32), blkT>>>(Wq, Bh, Bl, Dd, Dd);
    bgemm_kernel<3><<<gdd, 512, SMEM_B>>>(Ah, Al, Bh, Bl, bq, nullptr, nullptr, qh, ql, Dd, Dd);
    convtrans_kernel<<<dim3(Dd/32, Dd/32), blkT>>>(Wk, Bh, Bl, Dd, Dd);
    bgemm_kernel<3><<<gdd, 512, SMEM_B>>>(Ah, Al, Bh, Bl, bk, nullptr, nullptr, kh, kl, Dd, Dd);
    convtrans_kernel<<<dim3(Dd/32, Dd/32), blkT>>>(Wv, Bh, Bl, Dd, Dd);
    bgemm_kernel<3><<<gdd, 512, SMEM_B>>>(Ah, Al, Bh, Bl, bv, nullptr, nullptr, vh, vl, Dd, Dd);

    dim3 gfa(Ss / 128, Bb * Hh);               // (8, 128)
    fattn_kernel<<<gfa, 256, FA_SMEM>>>(qh, ql, kh, kl, vh, vl, vlen, Ah, Al);

    convtrans_kernel<<<dim3(Dd/32, Dd/32), blkT>>>(Wo, Bh, Bl, Dd, Dd);
    bgemm_kernel<1><<<gdd, 512, SMEM_B>>>(Ah, Al, Bh, Bl, bo, h, mid, nullptr, nullptr, Dd, Dd);

    ln_split_kernel<<<MROWS, 256>>>(mid, g2, beta2, Ah, Al);

    convtrans_kernel<<<dim3(FFf/32, Dd/32), blkT>>>(W1, Bh, Bl, Dd, FFf);
    dim3 gff(FFf / 256, MROWS / 128);          // (16, 64)
    bgemm_kernel<4><<<gff, 512, SMEM_B>>>(Ah, Al, Bh, Bl, b1, nullptr, nullptr, fh, fl, FFf, Dd);

    convtrans_kernel<<<dim3(Dd/32, FFf/32), blkT>>>(W2, Bh, Bl, FFf, Dd);
    bgemm_kernel<1><<<gdd, 512, SMEM_B>>>(fh, fl, Bh, Bl, b2, mid, out, nullptr, nullptr, Dd, FFf);
}

// round 16
// speedup vs baseline: 1.5104x; 1.5104x over previous
#include <cuda_runtime.h>
#include <cuda_fp16.h>
#include <cuda_pipeline.h>
#include <mma.h>
#include <math.h>
#include <stdint.h>

using namespace nvcuda;

#define Bb 8
#define Ss 1024
#define Dd 1024
#define Hh 16
#define DHh 64
#define FFf 4096
#define LAYER 3
#define MROWS (Bb*Ss)   /* 8192 */

// ---------------- scratch (device globals; allocation-free rule) ----------------
__device__ float g_h  [MROWS*Dd];
__device__ float g_mid[MROWS*Dd];
__device__ __half g_f [(size_t)2*MROWS*FFf];   // ffn split hi|lo
__device__ __half g_Ah[(size_t)MROWS*FFf];
__device__ __half g_Al[(size_t)MROWS*FFf];
__device__ __half g_Bh[(size_t)FFf*Dd];        // weights: single fp16
__device__ __half g_qh[MROWS*Dd];
__device__ __half g_ql[MROWS*Dd];
__device__ __half g_kh[MROWS*Dd];              // K: single fp16
__device__ __half g_vh[MROWS*Dd];              // V: single fp16
__device__ int   g_is64;

// ==================== dtype detection ====================
__global__ void detect_kernel(const int* __restrict__ x) {
    __shared__ int any;
    if (threadIdx.x == 0) any = 0;
    __syncthreads();
    int local = 0;
    for (int i = threadIdx.x; i < 4096; i += blockDim.x)
        if (x[2*i + 1] != 0) local = 1;
    if (local) any = 1;
    __syncthreads();
    if (threadIdx.x == 0) g_is64 = (any == 0) ? 1 : 0;
}

// ==================== embed ====================
__global__ void embed_kernel(const int* __restrict__ x, const float* __restrict__ emb,
                             const float* __restrict__ pos, float* __restrict__ h) {
    int i = blockIdx.x * blockDim.x + threadIdx.x;
    if (i >= MROWS * (Dd/4)) return;
    int row = i >> 8;
    int dc  = i & 255;
    int s   = row & (Ss - 1);
    long long tok = g_is64 ? ((const long long*)x)[row] : (long long)x[row];
    float4 e = ((const float4*)emb)[(size_t)tok * 256 + dc];
    float4 p = ((const float4*)pos)[(size_t)s   * 256 + dc];
    float4 r;
    r.x = fmaf(e.x, 32.0f, p.x);
    r.y = fmaf(e.y, 32.0f, p.y);
    r.z = fmaf(e.z, 32.0f, p.z);
    r.w = fmaf(e.w, 32.0f, p.w);
    ((float4*)h)[i] = r;
}

// ==================== helpers ====================
__device__ __forceinline__ void split2(float v, __half& h, __half& l) {
    h = __float2half(v);
    l = __float2half(v - __half2float(h));
}

// ==================== layernorm with fused split-fp16 output ====================
__global__ __launch_bounds__(256)
void ln_split_kernel(const float* __restrict__ in, const float* __restrict__ gamma,
                     const float* __restrict__ beta, __half* __restrict__ oh,
                     __half* __restrict__ ol) {
    int row = blockIdx.x;
    int tid = threadIdx.x;
    const float4* xr = (const float4*)(in + (size_t)row * Dd);
    float4 v = xr[tid];
    float s1 = v.x + v.y + v.z + v.w;
    float s2 = v.x*v.x + v.y*v.y + v.z*v.z + v.w*v.w;
    #pragma unroll
    for (int o = 16; o; o >>= 1) {
        s1 += __shfl_xor_sync(0xffffffffu, s1, o);
        s2 += __shfl_xor_sync(0xffffffffu, s2, o);
    }
    __shared__ float a1[8], a2[8];
    int lane = tid & 31, wid = tid >> 5;
    if (lane == 0) { a1[wid] = s1; a2[wid] = s2; }
    __syncthreads();
    __shared__ float mS, invS;
    if (tid == 0) {
        float t1 = 0.f, t2 = 0.f;
        #pragma unroll
        for (int w = 0; w < 8; ++w) { t1 += a1[w]; t2 += a2[w]; }
        float mean = t1 * (1.0f / Dd);
        float var  = t2 * (1.0f / Dd) - mean * mean;
        mS = mean; invS = rsqrtf(var + 1e-5f);
    }
    __syncthreads();
    float mean = mS, inv = invS;
    float4 g4 = ((const float4*)gamma)[tid];
    float4 b4 = ((const float4*)beta)[tid];
    float o0 = (v.x - mean) * inv * g4.x + b4.x;
    float o1 = (v.y - mean) * inv * g4.y + b4.y;
    float o2 = (v.z - mean) * inv * g4.z + b4.z;
    float o3 = (v.w - mean) * inv * g4.w + b4.w;
    __half h0, h1, h2, h3, l0, l1, l2, l3;
    split2(o0, h0, l0); split2(o1, h1, l1);
    split2(o2, h2, l2); split2(o3, h3, l3);
    size_t base = (size_t)row * Dd + tid * 4;
    *(__half2*)(oh + base)     = __halves2half2(h0, h1);
    *(__half2*)(oh + base + 2) = __halves2half2(h2, h3);
    *(__half2*)(ol + base)     = __halves2half2(l0, l1);
    *(__half2*)(ol + base + 2) = __halves2half2(l2, l3);
}

// ==================== weight fp32 [K,N] -> fp16 transposed [N,K] ====================
__global__ void convtrans_kernel(const float* __restrict__ W, __half* __restrict__ TH,
                                 int K, int N) {
    __shared__ float t[32][33];
    int nb = blockIdx.x * 32, kb = blockIdx.y * 32;
    int tx = threadIdx.x, ty = threadIdx.y;
    for (int r = ty; r < 32; r += 8)
        t[r][tx] = W[(size_t)(kb + r) * N + nb + tx];
    __syncthreads();
    for (int r = ty; r < 32; r += 8) {
        size_t o = (size_t)(nb + r) * K + kb + tx;
        TH[o] = __float2half(t[tx][r]);
    }
}

// ==================== wmma fp16 2-term GEMM (128x256 tile, BK=64, 256 threads) ====================
#define WTSE 72
#define WTSB 144
#define A_TILE_B (128*WTSB)                 /* 18432 */
#define B_TILE_B (256*WTSB)                 /* 36864 */
#define STAGE_B  (2*A_TILE_B + B_TILE_B)    /* 73728 */
#define SMEM_B   (2*STAGE_B)                /* 147456 >= epilogue 133120 */

// EPI: 0:+bias->C  1:+bias+res->C  2:relu(+bias)->C  3:+bias->split  4:relu(+bias)->split
template<int EPI>
__global__ __launch_bounds__(256)
void bgemm_kernel(const __half* __restrict__ Ah, const __half* __restrict__ Al,
                  const __half* __restrict__ Bh,
                  const float* __restrict__ bias, const float* __restrict__ res,
                  float* __restrict__ C, __half* __restrict__ Oh,
                  __half* __restrict__ Ol, int N, int K) {
    extern __shared__ __align__(128) char smem[];
    int tid = threadIdx.x, wid = tid >> 5;
    int rowBase = blockIdx.y * 128, colBase = blockIdx.x * 256;
    int m0 = (wid >> 2) * 64, n0 = (wid & 3) * 64;

    // 16 x 16B chunks per stage per thread (4096 total)
    const __half* gsrc[16];
    int soff[16];
    #pragma unroll
    for (int i = 0; i < 16; ++i) {
        int v = tid + (i << 8);
        if (v < 2048) {
            int t2 = v >> 10, idx = v & 1023, row = idx >> 3, c = idx & 7;
            gsrc[i] = (t2 ? Al : Ah) + (size_t)(rowBase + row) * K + c * 8;
            soff[i] = t2 * A_TILE_B + row * WTSB + c * 16;
        } else {
            int w = v - 2048, row = w >> 3, c = w & 7;
            gsrc[i] = Bh + (size_t)(colBase + row) * K + c * 8;
            soff[i] = 2 * A_TILE_B + row * WTSB + c * 16;
        }
    }

    wmma::fragment<wmma::accumulator, 16, 16, 16, float> acc[4][4];
    #pragma unroll
    for (int mf = 0; mf < 4; ++mf)
        #pragma unroll
        for (int nf = 0; nf < 4; ++nf)
            wmma::fill_fragment(acc[mf][nf], 0.0f);

    const int nch = K >> 6;
    #pragma unroll
    for (int i = 0; i < 16; ++i)
        __pipeline_memcpy_async(smem + soff[i], gsrc[i], 16);
    __pipeline_commit();
    #pragma unroll
    for (int i = 0; i < 16; ++i)
        __pipeline_memcpy_async(smem + STAGE_B + soff[i], gsrc[i] + 64, 16);
    __pipeline_commit();

    for (int ch = 0; ch < nch; ++ch) {
        if (ch + 2 <= nch) __pipeline_wait_prior(1);
        else               __pipeline_wait_prior(0);
        __syncthreads();
        char* stage = smem + (ch & 1) * STAGE_B;
        const __half* At_h = (const __half*)(stage);
        const __half* At_l = (const __half*)(stage + A_TILE_B);
        const __half* Bt   = (const __half*)(stage + 2 * A_TILE_B);
        #pragma unroll
        for (int ks = 0; ks < 4; ++ks) {
            wmma::fragment<wmma::matrix_b, 16, 16, 16, half, wmma::col_major> bfr[4];
            #pragma unroll
            for (int nf = 0; nf < 4; ++nf)
                wmma::load_matrix_sync(bfr[nf], Bt + (n0 + nf * 16) * WTSE + ks * 16, WTSE);
            #pragma unroll
            for (int mf = 0; mf < 4; ++mf) {
                wmma::fragment<wmma::matrix_a, 16, 16, 16, half, wmma::row_major> fa, fl2;
                wmma::load_matrix_sync(fa,  At_h + (m0 + mf * 16) * WTSE + ks * 16, WTSE);
                wmma::load_matrix_sync(fl2, At_l + (m0 + mf * 16) * WTSE + ks * 16, WTSE);
                #pragma unroll
                for (int nf = 0; nf < 4; ++nf)
                    wmma::mma_sync(acc[mf][nf], fa, bfr[nf], acc[mf][nf]);
                #pragma unroll
                for (int nf = 0; nf < 4; ++nf)
                    wmma::mma_sync(acc[mf][nf], fl2, bfr[nf], acc[mf][nf]);
            }
        }
        __syncthreads();
        if (ch + 2 < nch) {
            #pragma unroll
            for (int i = 0; i < 16; ++i)
                __pipeline_memcpy_async(smem + (ch & 1) * STAGE_B + soff[i],
                                        gsrc[i] + (size_t)(ch + 2) * 64, 16);
            __pipeline_commit();
        }
    }

    float* sf = (float*)smem;
    #pragma unroll
    for (int mf = 0; mf < 4; ++mf)
        #pragma unroll
        for (int nf = 0; nf < 4; ++nf)
            wmma::store_matrix_sync(sf + (m0 + mf * 16) * 260 + n0 + nf * 16,
                                    acc[mf][nf], 260, wmma::mem_row_major);
    __syncthreads();
    #pragma unroll
    for (int i = 0; i < 32; ++i) {
        int v = tid + (i << 8);
        int r = v >> 6, c4 = (v & 63) * 4;
        float4 val = *(float4*)(sf + r * 260 + c4);
        int col = colBase + c4;
        float4 bv = *(const float4*)(bias + col);
        val.x += bv.x; val.y += bv.y; val.z += bv.z; val.w += bv.w;
        size_t o = (size_t)(rowBase + r) * N + col;
        if (EPI == 1) {
            float4 rv = *(const float4*)(res + o);
            val.x += rv.x; val.y += rv.y; val.z += rv.z; val.w += rv.w;
        }
        if (EPI == 2 || EPI == 4) {
            val.x = fmaxf(val.x, 0.f); val.y = fmaxf(val.y, 0.f);
            val.z = fmaxf(val.z, 0.f); val.w = fmaxf(val.w, 0.f);
        }
        if (EPI <= 2) {
            *(float4*)(C + o) = val;
        } else {
            __half h0, h1, h2, h3, l0, l1, l2, l3;
            split2(val.x, h0, l0); split2(val.y, h1, l1);
            split2(val.z, h2, l2); split2(val.w, h3, l3);
            *(__half2*)(Oh + o)     = __halves2half2(h0, h1);
            *(__half2*)(Oh + o + 2) = __halves2half2(h2, h3);
            *(__half2*)(Ol + o)     = __halves2half2(l0, l1);
            *(__half2*)(Ol + o + 2) = __halves2half2(l2, l3);
        }
    }
}

// ==================== fused attention (scores + softmax + ctx), fp16 2-term ====================
#define FTSE 72
#define FTSB 144
#define FA_QH 0            /* 18432 */
#define FA_QL 18432
#define FA_K  36864        /* K single: 18432 */
#define FA_SV 55296        /* S: 128x132 fp32 = 67584 ; V single aliased here */
#define FA_PH 122880       /* P hi: 128x136 fp16 = 34816 */
#define FA_PL 157696
#define FA_RS 192512
#define FA_SMEM 193024

__global__ __launch_bounds__(256)
void fattn_kernel(const __half* __restrict__ qh, const __half* __restrict__ ql,
                  const __half* __restrict__ kh, const __half* __restrict__ vh,
                  const int* __restrict__ vlen,
                  __half* __restrict__ Oh, __half* __restrict__ Ol) {
    extern __shared__ __align__(128) char smem[];
    int bh = blockIdx.y;
    int b = bh >> 4, hh = bh & 15;
    int i0 = blockIdx.x * 128;
    int vl = g_is64 ? (int)((const long long*)vlen)[b] : vlen[b];
    int nch = (vl + 127) >> 7;
    int tid = threadIdx.x, wid = tid >> 5, lane = tid & 31;
    int sm0 = (wid >> 2) * 64, sn0 = (wid & 3) * 32;
    int om0 = (wid >> 1) * 32, on0 = (wid & 1) * 32;
    int myrow0 = wid * 16;

    // load Q (split) once
    #pragma unroll
    for (int i = 0; i < 8; ++i) {
        int v = tid + (i << 8);
        int split = v >> 10, rem = v & 1023, r = rem >> 3, c = rem & 7;
        const __half* src = (split ? ql : qh) + (size_t)(b * Ss + i0 + r) * Dd + hh * 64 + c * 8;
        *(uint4*)(smem + split * 18432 + r * FTSB + c * 16) = *(const uint4*)src;
    }

    wmma::fragment<wmma::accumulator, 16, 16, 16, float> oacc[2][2];
    #pragma unroll
    for (int mf = 0; mf < 2; ++mf)
        #pragma unroll
        for (int nf = 0; nf < 2; ++nf)
            wmma::fill_fragment(oacc[mf][nf], 0.0f);
    float psum[16];
    #pragma unroll
    for (int rr = 0; rr < 16; ++rr) psum[rr] = 0.f;

    for (int ch = 0; ch < nch; ++ch) {
        int j0 = ch * 128;
        // load K (single)
        #pragma unroll
        for (int i = 0; i < 4; ++i) {
            int v = tid + (i << 8);
            int r = v >> 3, c = v & 7;
            const __half* src = kh + (size_t)(b * Ss + j0 + r) * Dd + hh * 64 + c * 8;
            *(uint4*)(smem + FA_K + r * FTSB + c * 16) = *(const uint4*)src;
        }
        __syncthreads();
        // S = q.k^T / 8  (2-term)
        {
            wmma::fragment<wmma::accumulator, 16, 16, 16, float> sacc[4][2];
            #pragma unroll
            for (int mf = 0; mf < 4; ++mf)
                #pragma unroll
                for (int nf = 0; nf < 2; ++nf)
                    wmma::fill_fragment(sacc[mf][nf], 0.0f);
            const __half* Qh = (const __half*)(smem + FA_QH);
            const __half* Ql = (const __half*)(smem + FA_QL);
            const __half* Kt = (const __half*)(smem + FA_K);
            #pragma unroll
            for (int ks = 0; ks < 4; ++ks) {
                wmma::fragment<wmma::matrix_a, 16, 16, 16, half, wmma::row_major> ahf[4], alf[4];
                wmma::fragment<wmma::matrix_b, 16, 16, 16, half, wmma::col_major> bhf[2];
                #pragma unroll
                for (int mf = 0; mf < 4; ++mf) {
                    wmma::load_matrix_sync(ahf[mf], Qh + (sm0 + mf * 16) * FTSE + ks * 16, FTSE);
                    wmma::load_matrix_sync(alf[mf], Ql + (sm0 + mf * 16) * FTSE + ks * 16, FTSE);
                }
                #pragma unroll
                for (int nf = 0; nf < 2; ++nf)
                    wmma::load_matrix_sync(bhf[nf], Kt + (sn0 + nf * 16) * FTSE + ks * 16, FTSE);
                #pragma unroll
                for (int mf = 0; mf < 4; ++mf)
                    #pragma unroll
                    for (int nf = 0; nf < 2; ++nf) {
                        wmma::mma_sync(sacc[mf][nf], ahf[mf], bhf[nf], sacc[mf][nf]);
                        wmma::mma_sync(sacc[mf][nf], alf[mf], bhf[nf], sacc[mf][nf]);
                    }
            }
            float* S = (float*)(smem + FA_SV);
            #pragma unroll
            for (int mf = 0; mf < 4; ++mf)
                #pragma unroll
                for (int nf = 0; nf < 2; ++nf) {
                    #pragma unroll
                    for (int t = 0; t < sacc[mf][nf].num_elements; ++t)
                        sacc[mf][nf].x[t] *= 0.125f;
                    wmma::store_matrix_sync(S + (sm0 + mf * 16) * 132 + sn0 + nf * 16,
                                            sacc[mf][nf], 132, wmma::mem_row_major);
                }
        }
        __syncthreads();
        // exp + mask + psum + split-fp16 P
        {
            const float* S = (const float*)(smem + FA_SV);
            int jb = j0 + lane * 4;
            #pragma unroll
            for (int rr = 0; rr < 16; ++rr) {
                int row = myrow0 + rr;
                float4 sv = *(const float4*)(S + row * 132 + lane * 4);
                float p0 = (jb + 0 < vl) ? __expf(sv.x) : 0.f;
                float p1 = (jb + 1 < vl) ? __expf(sv.y) : 0.f;
                float p2 = (jb + 2 < vl) ? __expf(sv.z) : 0.f;
                float p3 = (jb + 3 < vl) ? __expf(sv.w) : 0.f;
                psum[rr] += (p0 + p1) + (p2 + p3);
                __half h0, h1, h2, h3, l0, l1, l2, l3;
                split2(p0, h0, l0); split2(p1, h1, l1);
                split2(p2, h2, l2); split2(p3, h3, l3);
                int po = row * 272 + lane * 8;
                *(__half2*)(smem + FA_PH + po)     = __halves2half2(h0, h1);
                *(__half2*)(smem + FA_PH + po + 4) = __halves2half2(h2, h3);
                *(__half2*)(smem + FA_PL + po)     = __halves2half2(l0, l1);
                *(__half2*)(smem + FA_PL + po + 4) = __halves2half2(l2, l3);
            }
        }
        __syncthreads();
        // load V (single) into the dead S region
        #pragma unroll
        for (int i = 0; i < 4; ++i) {
            int v = tid + (i << 8);
            int r = v >> 3, c = v & 7;
            const __half* src = vh + (size_t)(b * Ss + j0 + r) * Dd + hh * 64 + c * 8;
            *(uint4*)(smem + FA_SV + r * FTSB + c * 16) = *(const uint4*)src;
        }
        __syncthreads();
        // O += P.V  (2-term)
        {
            const __half* Ph = (const __half*)(smem + FA_PH);
            const __half* Pl = (const __half*)(smem + FA_PL);
            const __half* Vt = (const __half*)(smem + FA_SV);
            #pragma unroll
            for (int ks = 0; ks < 8; ++ks) {
                wmma::fragment<wmma::matrix_a, 16, 16, 16, half, wmma::row_major> fph[2], fpl[2];
                wmma::fragment<wmma::matrix_b, 16, 16, 16, half, wmma::row_major> fvh[2];
                #pragma unroll
                for (int mf = 0; mf < 2; ++mf) {
                    wmma::load_matrix_sync(fph[mf], Ph + (om0 + mf * 16) * 136 + ks * 16, 136);
                    wmma::load_matrix_sync(fpl[mf], Pl + (om0 + mf * 16) * 136 + ks * 16, 136);
                }
                #pragma unroll
                for (int nf = 0; nf < 2; ++nf)
                    wmma::load_matrix_sync(fvh[nf], Vt + (ks * 16) * FTSE + on0 + nf * 16, FTSE);
                #pragma unroll
                for (int mf = 0; mf < 2; ++mf)
                    #pragma unroll
                    for (int nf = 0; nf < 2; ++nf) {
                        wmma::mma_sync(oacc[mf][nf], fph[mf], fvh[nf], oacc[mf][nf]);
                        wmma::mma_sync(oacc[mf][nf], fpl[mf], fvh[nf], oacc[mf][nf]);
                    }
            }
        }
        __syncthreads();
    }

    {
        float* rinv = (float*)(smem + FA_RS);
        #pragma unroll
        for (int rr = 0; rr < 16; ++rr) {
            float s = psum[rr];
            #pragma unroll
            for (int o = 16; o; o >>= 1) s += __shfl_xor_sync(0xffffffffu, s, o);
            if (lane == 0) rinv[myrow0 + rr] = 1.0f / s;
        }
    }
    float* sf = (float*)(smem + FA_SV);
    #pragma unroll
    for (int mf = 0; mf < 2; ++mf)
        #pragma unroll
        for (int nf = 0; nf < 2; ++nf)
            wmma::store_matrix_sync(sf + (om0 + mf * 16) * 68 + on0 + nf * 16,
                                    oacc[mf][nf], 68, wmma::mem_row_major);
    __syncthreads();
    const float* rinv = (const float*)(smem + FA_RS);
    #pragma unroll
    for (int i = 0; i < 8; ++i) {
        int v = tid + (i << 8);
        int r = v >> 4, c4 = (v & 15) * 4;
        float inv = rinv[r];
        float4 val = *(float4*)(sf + r * 68 + c4);
        val.x *= inv; val.y *= inv; val.z *= inv; val.w *= inv;
        size_t o = (size_t)(b * Ss + i0 + r) * Dd + hh * 64 + c4;
        __half h0, h1, h2, h3, l0, l1, l2, l3;
        split2(val.x, h0, l0); split2(val.y, h1, l1);
        split2(val.z, h2, l2); split2(val.w, h3, l3);
        *(__half2*)(Oh + o)     = __halves2half2(h0, h1);
        *(__half2*)(Oh + o + 2) = __halves2half2(h2, h3);
        *(__half2*)(Ol + o)     = __halves2half2(l0, l1);
        *(__half2*)(Ol + o + 2) = __halves2half2(l2, l3);
    }
}

// ==================== q/k/v epilogue splitter note ====================
// QKV GEMMs write split outputs for Q (needs 2-term LHS in scores) but K and V
// only need single fp16. We reuse EPI=3 (split) for Q and a single-output EPI.
// EPI 5: +bias -> single fp16 Oh only.
template<int EPI> __global__ void bgemm_kernel_single_tag();  // (doc only)

// ==================== launch ====================
extern "C" void kernel_launch(void* const* d_in, const int* in_sizes, int n_in,
                              void* d_out, int out_size) {
    const int*   x    = (const int*)d_in[0];
    const int*   vlen = (const int*)d_in[1];
    const float* emb  = (const float*)d_in[2];
    const float* pos  = (const float*)d_in[3];
    const float* Wq = (const float*)d_in[4]  + (size_t)LAYER * Dd * Dd;
    const float* bq = (const float*)d_in[5]  + LAYER * Dd;
    const float* Wk = (const float*)d_in[6]  + (size_t)LAYER * Dd * Dd;
    const float* bk = (const float*)d_in[7]  + LAYER * Dd;
    const float* Wv = (const float*)d_in[8]  + (size_t)LAYER * Dd * Dd;
    const float* bv = (const float*)d_in[9]  + LAYER * Dd;
    const float* Wo = (const float*)d_in[10] + (size_t)LAYER * Dd * Dd;
    const float* bo = (const float*)d_in[11] + LAYER * Dd;
    const float* W1 = (const float*)d_in[12] + (size_t)LAYER * Dd * FFf;
    const float* b1 = (const float*)d_in[13] + LAYER * FFf;
    const float* W2 = (const float*)d_in[14] + (size_t)LAYER * FFf * Dd;
    const float* b2 = (const float*)d_in[15] + LAYER * Dd;
    const float* g1    = (const float*)d_in[16] + LAYER * Dd;
    const float* beta1 = (const float*)d_in[17] + LAYER * Dd;
    const float* g2    = (const float*)d_in[18] + LAYER * Dd;
    const float* beta2 = (const float*)d_in[19] + LAYER * Dd;
    float* out = (float*)d_out;

    float *h, *mid;
    __half *f, *Ah, *Al, *Bh, *qh, *ql, *kh, *vh;
    cudaGetSymbolAddress((void**)&h,   g_h);
    cudaGetSymbolAddress((void**)&mid, g_mid);
    cudaGetSymbolAddress((void**)&f,   g_f);
    cudaGetSymbolAddress((void**)&Ah,  g_Ah);
    cudaGetSymbolAddress((void**)&Al,  g_Al);
    cudaGetSymbolAddress((void**)&Bh,  g_Bh);
    cudaGetSymbolAddress((void**)&qh,  g_qh);
    cudaGetSymbolAddress((void**)&ql,  g_ql);
    cudaGetSymbolAddress((void**)&kh,  g_kh);
    cudaGetSymbolAddress((void**)&vh,  g_vh);
    __half* fh = f;
    __half* fl = f + (size_t)MROWS * FFf;

    cudaFuncSetAttribute(bgemm_kernel<1>, cudaFuncAttributeMaxDynamicSharedMemorySize, SMEM_B);
    cudaFuncSetAttribute(bgemm_kernel<3>, cudaFuncAttributeMaxDynamicSharedMemorySize, SMEM_B);
    cudaFuncSetAttribute(bgemm_kernel<4>, cudaFuncAttributeMaxDynamicSharedMemorySize, SMEM_B);
    cudaFuncSetAttribute(fattn_kernel, cudaFuncAttributeMaxDynamicSharedMemorySize, FA_SMEM);

    detect_kernel<<<1, 256>>>(x);
    embed_kernel<<<(MROWS * (Dd/4)) / 256, 256>>>(x, emb, pos, h);
    ln_split_kernel<<<MROWS, 256>>>(h, g1, beta1, Ah, Al);

    dim3 blkT(32, 8);
    dim3 gdd(Dd / 256, MROWS / 128);           // (4, 64)

    // Q needs split output (LHS of scores GEMM); K and V only need hi
    // (the lo buffer for K/V is written but unused — reuse ql as scratch lo).
    convtrans_kernel<<<dim3(Dd/32, Dd/32), blkT>>>(Wq, Bh, Dd, Dd);
    bgemm_kernel<3><<<gdd, 256, SMEM_B>>>(Ah, Al, Bh, bq, nullptr, nullptr, qh, ql, Dd, Dd);
    convtrans_kernel<<<dim3(Dd/32, Dd/32), blkT>>>(Wk, Bh, Dd, Dd);
    bgemm_kernel<3><<<gdd, 256, SMEM_B>>>(Ah, Al, Bh, bk, nullptr, nullptr, kh, fh, Dd, Dd);
    convtrans_kernel<<<dim3(Dd/32, Dd/32), blkT>>>(Wv, Bh, Dd, Dd);
    bgemm_kernel<3><<<gdd, 256, SMEM_B>>>(Ah, Al, Bh, bv, nullptr, nullptr, vh, fh, Dd, Dd);

    dim3 gfa(Ss / 128, Bb * Hh);               // (8, 128)
    fattn_kernel<<<gfa, 256, FA_SMEM>>>(qh, ql, kh, vh, vlen, Ah, Al);

    convtrans_kernel<<<dim3(Dd/32, Dd/32), blkT>>>(Wo, Bh, Dd, Dd);
    bgemm_kernel<1><<<gdd, 256, SMEM_B>>>(Ah, Al, Bh, bo, h, mid, nullptr, nullptr, Dd, Dd);

    ln_split_kernel<<<MROWS, 256>>>(mid, g2, beta2, Ah, Al);

    convtrans_kernel<<<dim3(FFf/32, Dd/32), blkT>>>(W1, Bh, Dd, FFf);
    dim3 gff(FFf / 256, MROWS / 128);          // (16, 64)
    bgemm_kernel<4><<<gff, 256, SMEM_B>>>(Ah, Al, Bh, b1, nullptr, nullptr, fh, fl, FFf, Dd);

    convtrans_kernel<<<dim3(Dd/32, FFf/32), blkT>>>(W2, Bh, FFf, Dd);
    bgemm_kernel<1><<<gdd, 256, SMEM_B>>>(fh, fl, Bh, b2, mid, out, nullptr, nullptr, Dd, FFf);
}

// round 17
// speedup vs baseline: 2.3538x; 1.5584x over previous
#include <cuda_runtime.h>
#include <cuda_fp16.h>
#include <cuda_pipeline.h>
#include <mma.h>
#include <math.h>
#include <stdint.h>

using namespace nvcuda;

#define Bb 8
#define Ss 1024
#define Dd 1024
#define Hh 16
#define DHh 64
#define FFf 4096
#define LAYER 3
#define MROWS (Bb*Ss)   /* 8192 */

// ---------------- scratch (device globals; allocation-free rule) ----------------
__device__ float g_h  [MROWS*Dd];
__device__ float g_mid[MROWS*Dd];
__device__ __half g_f [(size_t)MROWS*FFf];     // ffn single fp16
__device__ __half g_A [(size_t)MROWS*Dd];      // activations single fp16
__device__ __half g_Bw[(size_t)FFf*Dd];        // weights single fp16
__device__ __half g_q [MROWS*Dd];
__device__ __half g_k [MROWS*Dd];
__device__ __half g_v [MROWS*Dd];
__device__ int   g_is64;

// ==================== dtype detection ====================
__global__ void detect_kernel(const int* __restrict__ x) {
    __shared__ int any;
    if (threadIdx.x == 0) any = 0;
    __syncthreads();
    int local = 0;
    for (int i = threadIdx.x; i < 4096; i += blockDim.x)
        if (x[2*i + 1] != 0) local = 1;
    if (local) any = 1;
    __syncthreads();
    if (threadIdx.x == 0) g_is64 = (any == 0) ? 1 : 0;
}

// ==================== embed ====================
__global__ void embed_kernel(const int* __restrict__ x, const float* __restrict__ emb,
                             const float* __restrict__ pos, float* __restrict__ h) {
    int i = blockIdx.x * blockDim.x + threadIdx.x;
    if (i >= MROWS * (Dd/4)) return;
    int row = i >> 8;
    int dc  = i & 255;
    int s   = row & (Ss - 1);
    long long tok = g_is64 ? ((const long long*)x)[row] : (long long)x[row];
    float4 e = ((const float4*)emb)[(size_t)tok * 256 + dc];
    float4 p = ((const float4*)pos)[(size_t)s   * 256 + dc];
    float4 r;
    r.x = fmaf(e.x, 32.0f, p.x);
    r.y = fmaf(e.y, 32.0f, p.y);
    r.z = fmaf(e.z, 32.0f, p.z);
    r.w = fmaf(e.w, 32.0f, p.w);
    ((float4*)h)[i] = r;
}

// ==================== layernorm with fused fp16 output ====================
__global__ __launch_bounds__(256)
void ln_h_kernel(const float* __restrict__ in, const float* __restrict__ gamma,
                 const float* __restrict__ beta, __half* __restrict__ oh) {
    int row = blockIdx.x;
    int tid = threadIdx.x;
    const float4* xr = (const float4*)(in + (size_t)row * Dd);
    float4 v = xr[tid];
    float s1 = v.x + v.y + v.z + v.w;
    float s2 = v.x*v.x + v.y*v.y + v.z*v.z + v.w*v.w;
    #pragma unroll
    for (int o = 16; o; o >>= 1) {
        s1 += __shfl_xor_sync(0xffffffffu, s1, o);
        s2 += __shfl_xor_sync(0xffffffffu, s2, o);
    }
    __shared__ float a1[8], a2[8];
    int lane = tid & 31, wid = tid >> 5;
    if (lane == 0) { a1[wid] = s1; a2[wid] = s2; }
    __syncthreads();
    __shared__ float mS, invS;
    if (tid == 0) {
        float t1 = 0.f, t2 = 0.f;
        #pragma unroll
        for (int w = 0; w < 8; ++w) { t1 += a1[w]; t2 += a2[w]; }
        float mean = t1 * (1.0f / Dd);
        float var  = t2 * (1.0f / Dd) - mean * mean;
        mS = mean; invS = rsqrtf(var + 1e-5f);
    }
    __syncthreads();
    float mean = mS, inv = invS;
    float4 g4 = ((const float4*)gamma)[tid];
    float4 b4 = ((const float4*)beta)[tid];
    float o0 = (v.x - mean) * inv * g4.x + b4.x;
    float o1 = (v.y - mean) * inv * g4.y + b4.y;
    float o2 = (v.z - mean) * inv * g4.z + b4.z;
    float o3 = (v.w - mean) * inv * g4.w + b4.w;
    size_t base = (size_t)row * Dd + tid * 4;
    *(__half2*)(oh + base)     = __halves2half2(__float2half(o0), __float2half(o1));
    *(__half2*)(oh + base + 2) = __halves2half2(__float2half(o2), __float2half(o3));
}

// ==================== weight fp32 [K,N] -> fp16 transposed [N,K] ====================
__global__ void convtrans_kernel(const float* __restrict__ W, __half* __restrict__ TH,
                                 int K, int N) {
    __shared__ float t[32][33];
    int nb = blockIdx.x * 32, kb = blockIdx.y * 32;
    int tx = threadIdx.x, ty = threadIdx.y;
    for (int r = ty; r < 32; r += 8)
        t[r][tx] = W[(size_t)(kb + r) * N + nb + tx];
    __syncthreads();
    for (int r = ty; r < 32; r += 8) {
        size_t o = (size_t)(nb + r) * K + kb + tx;
        TH[o] = __float2half(t[tx][r]);
    }
}

// ==================== wmma fp16 single GEMM (128x256 tile, BK=64, 256 threads) ====================
#define WTSE 72
#define WTSB 144
#define A_TILE_B (128*WTSB)                 /* 18432 */
#define B_TILE_B (256*WTSB)                 /* 36864 */
#define STAGE_B  (A_TILE_B + B_TILE_B)      /* 55296 */
#define SMEM_B   133632                     /* >= max(2*STAGE_B, 128*260*4) */

// EPI: 0:+bias->C  1:+bias+res->C  2:relu(+bias)->C  3:+bias->half  4:relu(+bias)->half
template<int EPI>
__global__ __launch_bounds__(256)
void bgemm_kernel(const __half* __restrict__ A, const __half* __restrict__ B,
                  const float* __restrict__ bias, const float* __restrict__ res,
                  float* __restrict__ C, __half* __restrict__ O, int N, int K) {
    extern __shared__ __align__(128) char smem[];
    int tid = threadIdx.x, wid = tid >> 5;
    int rowBase = blockIdx.y * 128, colBase = blockIdx.x * 256;
    int m0 = (wid >> 2) * 64, n0 = (wid & 3) * 64;

    // 12 x 16B chunks per stage per thread (3072 total)
    const __half* gsrc[12];
    int soff[12];
    #pragma unroll
    for (int i = 0; i < 12; ++i) {
        int v = tid + (i << 8);
        if (v < 1024) {
            int row = v >> 3, c = v & 7;
            gsrc[i] = A + (size_t)(rowBase + row) * K + c * 8;
            soff[i] = row * WTSB + c * 16;
        } else {
            int w = v - 1024, row = w >> 3, c = w & 7;
            gsrc[i] = B + (size_t)(colBase + row) * K + c * 8;
            soff[i] = A_TILE_B + row * WTSB + c * 16;
        }
    }

    wmma::fragment<wmma::accumulator, 16, 16, 16, float> acc[4][4];
    #pragma unroll
    for (int mf = 0; mf < 4; ++mf)
        #pragma unroll
        for (int nf = 0; nf < 4; ++nf)
            wmma::fill_fragment(acc[mf][nf], 0.0f);

    const int nch = K >> 6;
    #pragma unroll
    for (int i = 0; i < 12; ++i)
        __pipeline_memcpy_async(smem + soff[i], gsrc[i], 16);
    __pipeline_commit();
    #pragma unroll
    for (int i = 0; i < 12; ++i)
        __pipeline_memcpy_async(smem + STAGE_B + soff[i], gsrc[i] + 64, 16);
    __pipeline_commit();

    for (int ch = 0; ch < nch; ++ch) {
        if (ch + 2 <= nch) __pipeline_wait_prior(1);
        else               __pipeline_wait_prior(0);
        __syncthreads();
        char* stage = smem + (ch & 1) * STAGE_B;
        const __half* At = (const __half*)(stage);
        const __half* Bt = (const __half*)(stage + A_TILE_B);
        #pragma unroll
        for (int ks = 0; ks < 4; ++ks) {
            wmma::fragment<wmma::matrix_b, 16, 16, 16, half, wmma::col_major> bfr[4];
            #pragma unroll
            for (int nf = 0; nf < 4; ++nf)
                wmma::load_matrix_sync(bfr[nf], Bt + (n0 + nf * 16) * WTSE + ks * 16, WTSE);
            #pragma unroll
            for (int mf = 0; mf < 4; ++mf) {
                wmma::fragment<wmma::matrix_a, 16, 16, 16, half, wmma::row_major> fa;
                wmma::load_matrix_sync(fa, At + (m0 + mf * 16) * WTSE + ks * 16, WTSE);
                #pragma unroll
                for (int nf = 0; nf < 4; ++nf)
                    wmma::mma_sync(acc[mf][nf], fa, bfr[nf], acc[mf][nf]);
            }
        }
        __syncthreads();
        if (ch + 2 < nch) {
            #pragma unroll
            for (int i = 0; i < 12; ++i)
                __pipeline_memcpy_async(smem + (ch & 1) * STAGE_B + soff[i],
                                        gsrc[i] + (size_t)(ch + 2) * 64, 16);
            __pipeline_commit();
        }
    }

    float* sf = (float*)smem;
    #pragma unroll
    for (int mf = 0; mf < 4; ++mf)
        #pragma unroll
        for (int nf = 0; nf < 4; ++nf)
            wmma::store_matrix_sync(sf + (m0 + mf * 16) * 260 + n0 + nf * 16,
                                    acc[mf][nf], 260, wmma::mem_row_major);
    __syncthreads();
    #pragma unroll
    for (int i = 0; i < 32; ++i) {
        int v = tid + (i << 8);
        int r = v >> 6, c4 = (v & 63) * 4;
        float4 val = *(float4*)(sf + r * 260 + c4);
        int col = colBase + c4;
        float4 bv = *(const float4*)(bias + col);
        val.x += bv.x; val.y += bv.y; val.z += bv.z; val.w += bv.w;
        size_t o = (size_t)(rowBase + r) * N + col;
        if (EPI == 1) {
            float4 rv = *(const float4*)(res + o);
            val.x += rv.x; val.y += rv.y; val.z += rv.z; val.w += rv.w;
        }
        if (EPI == 2 || EPI == 4) {
            val.x = fmaxf(val.x, 0.f); val.y = fmaxf(val.y, 0.f);
            val.z = fmaxf(val.z, 0.f); val.w = fmaxf(val.w, 0.f);
        }
        if (EPI <= 2) {
            *(float4*)(C + o) = val;
        } else {
            *(__half2*)(O + o)     = __halves2half2(__float2half(val.x), __float2half(val.y));
            *(__half2*)(O + o + 2) = __halves2half2(__float2half(val.z), __float2half(val.w));
        }
    }
}

// ==================== fused attention (single fp16 q/k/v/p) ====================
#define FTSE 72
#define FTSB 144
#define FA_Q  0            /* 18432 */
#define FA_K  18432        /* 18432 */
#define FA_SV 36864        /* S: 128x132 fp32 = 67584 ; V aliased here */
#define FA_P  104448       /* P: 128x136 fp16 = 34816 */
#define FA_RS 139264       /* 128 floats */
#define FA_SMEM 139776

__global__ __launch_bounds__(256)
void fattn_kernel(const __half* __restrict__ q, const __half* __restrict__ k,
                  const __half* __restrict__ vv, const int* __restrict__ vlen,
                  __half* __restrict__ O) {
    extern __shared__ __align__(128) char smem[];
    int bh = blockIdx.y;
    int b = bh >> 4, hh = bh & 15;
    int i0 = blockIdx.x * 128;
    int vl = g_is64 ? (int)((const long long*)vlen)[b] : vlen[b];
    int nch = (vl + 127) >> 7;
    int tid = threadIdx.x, wid = tid >> 5, lane = tid & 31;
    int sm0 = (wid >> 2) * 64, sn0 = (wid & 3) * 32;
    int om0 = (wid >> 1) * 32, on0 = (wid & 1) * 32;
    int myrow0 = wid * 16;

    // load Q once
    #pragma unroll
    for (int i = 0; i < 4; ++i) {
        int v = tid + (i << 8);
        int r = v >> 3, c = v & 7;
        const __half* src = q + (size_t)(b * Ss + i0 + r) * Dd + hh * 64 + c * 8;
        *(uint4*)(smem + FA_Q + r * FTSB + c * 16) = *(const uint4*)src;
    }

    wmma::fragment<wmma::accumulator, 16, 16, 16, float> oacc[2][2];
    #pragma unroll
    for (int mf = 0; mf < 2; ++mf)
        #pragma unroll
        for (int nf = 0; nf < 2; ++nf)
            wmma::fill_fragment(oacc[mf][nf], 0.0f);
    float psum[16];
    #pragma unroll
    for (int rr = 0; rr < 16; ++rr) psum[rr] = 0.f;

    for (int ch = 0; ch < nch; ++ch) {
        int j0 = ch * 128;
        #pragma unroll
        for (int i = 0; i < 4; ++i) {
            int v = tid + (i << 8);
            int r = v >> 3, c = v & 7;
            const __half* src = k + (size_t)(b * Ss + j0 + r) * Dd + hh * 64 + c * 8;
            *(uint4*)(smem + FA_K + r * FTSB + c * 16) = *(const uint4*)src;
        }
        __syncthreads();
        {
            wmma::fragment<wmma::accumulator, 16, 16, 16, float> sacc[4][2];
            #pragma unroll
            for (int mf = 0; mf < 4; ++mf)
                #pragma unroll
                for (int nf = 0; nf < 2; ++nf)
                    wmma::fill_fragment(sacc[mf][nf], 0.0f);
            const __half* Qt = (const __half*)(smem + FA_Q);
            const __half* Kt = (const __half*)(smem + FA_K);
            #pragma unroll
            for (int ks = 0; ks < 4; ++ks) {
                wmma::fragment<wmma::matrix_a, 16, 16, 16, half, wmma::row_major> af[4];
                wmma::fragment<wmma::matrix_b, 16, 16, 16, half, wmma::col_major> bf2[2];
                #pragma unroll
                for (int mf = 0; mf < 4; ++mf)
                    wmma::load_matrix_sync(af[mf], Qt + (sm0 + mf * 16) * FTSE + ks * 16, FTSE);
                #pragma unroll
                for (int nf = 0; nf < 2; ++nf)
                    wmma::load_matrix_sync(bf2[nf], Kt + (sn0 + nf * 16) * FTSE + ks * 16, FTSE);
                #pragma unroll
                for (int mf = 0; mf < 4; ++mf)
                    #pragma unroll
                    for (int nf = 0; nf < 2; ++nf)
                        wmma::mma_sync(sacc[mf][nf], af[mf], bf2[nf], sacc[mf][nf]);
            }
            float* S = (float*)(smem + FA_SV);
            #pragma unroll
            for (int mf = 0; mf < 4; ++mf)
                #pragma unroll
                for (int nf = 0; nf < 2; ++nf) {
                    #pragma unroll
                    for (int t = 0; t < sacc[mf][nf].num_elements; ++t)
                        sacc[mf][nf].x[t] *= 0.125f;
                    wmma::store_matrix_sync(S + (sm0 + mf * 16) * 132 + sn0 + nf * 16,
                                            sacc[mf][nf], 132, wmma::mem_row_major);
                }
        }
        __syncthreads();
        {
            const float* S = (const float*)(smem + FA_SV);
            int jb = j0 + lane * 4;
            #pragma unroll
            for (int rr = 0; rr < 16; ++rr) {
                int row = myrow0 + rr;
                float4 sv = *(const float4*)(S + row * 132 + lane * 4);
                float p0 = (jb + 0 < vl) ? __expf(sv.x) : 0.f;
                float p1 = (jb + 1 < vl) ? __expf(sv.y) : 0.f;
                float p2 = (jb + 2 < vl) ? __expf(sv.z) : 0.f;
                float p3 = (jb + 3 < vl) ? __expf(sv.w) : 0.f;
                psum[rr] += (p0 + p1) + (p2 + p3);
                int po = row * 272 + lane * 8;
                *(__half2*)(smem + FA_P + po)     = __halves2half2(__float2half(p0), __float2half(p1));
                *(__half2*)(smem + FA_P + po + 4) = __halves2half2(__float2half(p2), __float2half(p3));
            }
        }
        __syncthreads();
        #pragma unroll
        for (int i = 0; i < 4; ++i) {
            int v = tid + (i << 8);
            int r = v >> 3, c = v & 7;
            const __half* src = vv + (size_t)(b * Ss + j0 + r) * Dd + hh * 64 + c * 8;
            *(uint4*)(smem + FA_SV + r * FTSB + c * 16) = *(const uint4*)src;
        }
        __syncthreads();
        {
            const __half* Pt = (const __half*)(smem + FA_P);
            const __half* Vt = (const __half*)(smem + FA_SV);
            #pragma unroll
            for (int ks = 0; ks < 8; ++ks) {
                wmma::fragment<wmma::matrix_a, 16, 16, 16, half, wmma::row_major> fp[2];
                wmma::fragment<wmma::matrix_b, 16, 16, 16, half, wmma::row_major> fv[2];
                #pragma unroll
                for (int mf = 0; mf < 2; ++mf)
                    wmma::load_matrix_sync(fp[mf], Pt + (om0 + mf * 16) * 136 + ks * 16, 136);
                #pragma unroll
                for (int nf = 0; nf < 2; ++nf)
                    wmma::load_matrix_sync(fv[nf], Vt + (ks * 16) * FTSE + on0 + nf * 16, FTSE);
                #pragma unroll
                for (int mf = 0; mf < 2; ++mf)
                    #pragma unroll
                    for (int nf = 0; nf < 2; ++nf)
                        wmma::mma_sync(oacc[mf][nf], fp[mf], fv[nf], oacc[mf][nf]);
            }
        }
        __syncthreads();
    }

    {
        float* rinv = (float*)(smem + FA_RS);
        #pragma unroll
        for (int rr = 0; rr < 16; ++rr) {
            float s = psum[rr];
            #pragma unroll
            for (int o = 16; o; o >>= 1) s += __shfl_xor_sync(0xffffffffu, s, o);
            if (lane == 0) rinv[myrow0 + rr] = 1.0f / s;
        }
    }
    float* sf = (float*)(smem + FA_SV);
    #pragma unroll
    for (int mf = 0; mf < 2; ++mf)
        #pragma unroll
        for (int nf = 0; nf < 2; ++nf)
            wmma::store_matrix_sync(sf + (om0 + mf * 16) * 68 + on0 + nf * 16,
                                    oacc[mf][nf], 68, wmma::mem_row_major);
    __syncthreads();
    const float* rinv = (const float*)(smem + FA_RS);
    #pragma unroll
    for (int i = 0; i < 8; ++i) {
        int v = tid + (i << 8);
        int r = v >> 4, c4 = (v & 15) * 4;
        float inv = rinv[r];
        float4 val = *(float4*)(sf + r * 68 + c4);
        val.x *= inv; val.y *= inv; val.z *= inv; val.w *= inv;
        size_t o = (size_t)(b * Ss + i0 + r) * Dd + hh * 64 + c4;
        *(__half2*)(O + o)     = __halves2half2(__float2half(val.x), __float2half(val.y));
        *(__half2*)(O + o + 2) = __halves2half2(__float2half(val.z), __float2half(val.w));
    }
}

// ==================== launch ====================
extern "C" void kernel_launch(void* const* d_in, const int* in_sizes, int n_in,
                              void* d_out, int out_size) {
    const int*   x    = (const int*)d_in[0];
    const int*   vlen = (const int*)d_in[1];
    const float* emb  = (const float*)d_in[2];
    const float* pos  = (const float*)d_in[3];
    const float* Wq = (const float*)d_in[4]  + (size_t)LAYER * Dd * Dd;
    const float* bq = (const float*)d_in[5]  + LAYER * Dd;
    const float* Wk = (const float*)d_in[6]  + (size_t)LAYER * Dd * Dd;
    const float* bk = (const float*)d_in[7]  + LAYER * Dd;
    const float* Wv = (const float*)d_in[8]  + (size_t)LAYER * Dd * Dd;
    const float* bv = (const float*)d_in[9]  + LAYER * Dd;
    const float* Wo = (const float*)d_in[10] + (size_t)LAYER * Dd * Dd;
    const float* bo = (const float*)d_in[11] + LAYER * Dd;
    const float* W1 = (const float*)d_in[12] + (size_t)LAYER * Dd * FFf;
    const float* b1 = (const float*)d_in[13] + LAYER * FFf;
    const float* W2 = (const float*)d_in[14] + (size_t)LAYER * FFf * Dd;
    const float* b2 = (const float*)d_in[15] + LAYER * Dd;
    const float* g1    = (const float*)d_in[16] + LAYER * Dd;
    const float* beta1 = (const float*)d_in[17] + LAYER * Dd;
    const float* g2    = (const float*)d_in[18] + LAYER * Dd;
    const float* beta2 = (const float*)d_in[19] + LAYER * Dd;
    float* out = (float*)d_out;

    float *h, *mid;
    __half *f, *A, *Bw, *q, *k, *v;
    cudaGetSymbolAddress((void**)&h,   g_h);
    cudaGetSymbolAddress((void**)&mid, g_mid);
    cudaGetSymbolAddress((void**)&f,   g_f);
    cudaGetSymbolAddress((void**)&A,   g_A);
    cudaGetSymbolAddress((void**)&Bw,  g_Bw);
    cudaGetSymbolAddress((void**)&q,   g_q);
    cudaGetSymbolAddress((void**)&k,   g_k);
    cudaGetSymbolAddress((void**)&v,   g_v);

    cudaFuncSetAttribute(bgemm_kernel<1>, cudaFuncAttributeMaxDynamicSharedMemorySize, SMEM_B);
    cudaFuncSetAttribute(bgemm_kernel<3>, cudaFuncAttributeMaxDynamicSharedMemorySize, SMEM_B);
    cudaFuncSetAttribute(bgemm_kernel<4>, cudaFuncAttributeMaxDynamicSharedMemorySize, SMEM_B);
    cudaFuncSetAttribute(fattn_kernel, cudaFuncAttributeMaxDynamicSharedMemorySize, FA_SMEM);

    detect_kernel<<<1, 256>>>(x);
    embed_kernel<<<(MROWS * (Dd/4)) / 256, 256>>>(x, emb, pos, h);
    ln_h_kernel<<<MROWS, 256>>>(h, g1, beta1, A);

    dim3 blkT(32, 8);
    dim3 gdd(Dd / 256, MROWS / 128);           // (4, 64)

    convtrans_kernel<<<dim3(Dd/32, Dd/32), blkT>>>(Wq, Bw, Dd, Dd);
    bgemm_kernel<3><<<gdd, 256, SMEM_B>>>(A, Bw, bq, nullptr, nullptr, q, Dd, Dd);
    convtrans_kernel<<<dim3(Dd/32, Dd/32), blkT>>>(Wk, Bw, Dd, Dd);
    bgemm_kernel<3><<<gdd, 256, SMEM_B>>>(A, Bw, bk, nullptr, nullptr, k, Dd, Dd);
    convtrans_kernel<<<dim3(Dd/32, Dd/32), blkT>>>(Wv, Bw, Dd, Dd);
    bgemm_kernel<3><<<gdd, 256, SMEM_B>>>(A, Bw, bv, nullptr, nullptr, v, Dd, Dd);

    dim3 gfa(Ss / 128, Bb * Hh);               // (8, 128)
    fattn_kernel<<<gfa, 256, FA_SMEM>>>(q, k, v, vlen, A);

    convtrans_kernel<<<dim3(Dd/32, Dd/32), blkT>>>(Wo, Bw, Dd, Dd);
    bgemm_kernel<1><<<gdd, 256, SMEM_B>>>(A, Bw, bo, h, mid, nullptr, Dd, Dd);

    ln_h_kernel<<<MROWS, 256>>>(mid, g2, beta2, A);

    convtrans_kernel<<<dim3(FFf/32, Dd/32), blkT>>>(W1, Bw, Dd, FFf);
    dim3 gff(FFf / 256, MROWS / 128);          // (16, 64)
    bgemm_kernel<4><<<gff, 256, SMEM_B>>>(A, Bw, b1, nullptr, nullptr, f, FFf, Dd);

    convtrans_kernel<<<dim3(Dd/32, FFf/32), blkT>>>(W2, Bw, FFf, Dd);
    bgemm_kernel<1><<<gdd, 256, SMEM_B>>>(f, Bw, b2, mid, out, nullptr, Dd, FFf);
}